// round 11
// baseline (speedup 1.0000x reference)
#include <cuda_runtime.h>

// YOLOv1 loss, GB300 sm_103a — persistent 64-thread blocks, THREE-stage
// cp.async pipeline (wait never drains the stream), balanced contiguous
// per-block tile chunks.
//
// pred:   (16384, 7, 7, 30) f32   d_in[0]
// target: (16384, 7, 7, 30) f32   d_in[1]
// out:    scalar f32
//
// smem/block = 3 stages x 2 tensors x 64 cells x 120B = 46080B -> 4 blocks/SM.
// Schedule per tile k: wait_group(1)  [k done, k+1 still in flight]
//                      -> barrier -> prefetch(k+2) -> compute(k).

#define N_BATCH 16384
#define N_CELLS (N_BATCH * 49)            // 802816
#define TPB 64
#define TILE 64                            // cells per tile (1 per thread)
#define TILE_FLOATS (TILE * 30)            // 1920 floats per tensor per tile
#define VEC4_PER_TENSOR (TILE_FLOATS / 4)  // 480
#define NTILES (N_CELLS / TILE)            // 12544 (exact)
#define BLOCKS_PER_SM 4
#define GRID (BLOCKS_PER_SM * 148)         // 592 persistent blocks
#define NSTAGE 3

__device__ double g_acc;
__device__ unsigned int g_count;

__device__ __forceinline__ void cp16(void* smem_dst, const void* gmem_src) {
    unsigned int s = (unsigned int)__cvta_generic_to_shared(smem_dst);
    asm volatile("cp.async.cg.shared.global [%0], [%1], 16;\n"
                 :: "r"(s), "l"(gmem_src) : "memory");
}
__device__ __forceinline__ void cp_commit() {
    asm volatile("cp.async.commit_group;\n" ::: "memory");
}
__device__ __forceinline__ void cp_wait1() {
    asm volatile("cp.async.wait_group 1;\n" ::: "memory");
}
__device__ __forceinline__ void cp_wait0() {
    asm volatile("cp.async.wait_group 0;\n" ::: "memory");
}

__global__ void __launch_bounds__(TPB, BLOCKS_PER_SM) yolo_loss_kernel(
    const float* __restrict__ pred,
    const float* __restrict__ targ,
    float* __restrict__ out)
{
    __shared__ __align__(16) float sp[NSTAGE][TILE_FLOATS];
    __shared__ __align__(16) float st[NSTAGE][TILE_FLOATS];
    __shared__ float warpsum[TPB / 32];
    __shared__ unsigned int s_ticket;

    const int tid = threadIdx.x;

    // ---- prefetch: tile -> stage buffer (coalesced float4 LDGSTS) ----
    auto prefetch = [&](int buf, int tile) {
        const float4* gp = (const float4*)(pred + (size_t)tile * TILE_FLOATS);
        const float4* gt = (const float4*)(targ + (size_t)tile * TILE_FLOATS);
        float4* s4p = (float4*)sp[buf];
        float4* s4t = (float4*)st[buf];
#pragma unroll
        for (int i = 0; i < 7; i++) {            // 7*64 = 448 of 480
            cp16(s4p + tid + i * TPB, gp + tid + i * TPB);
            cp16(s4t + tid + i * TPB, gt + tid + i * TPB);
        }
        if (tid < VEC4_PER_TENSOR - 7 * TPB) {   // remaining 32
            cp16(s4p + tid + 7 * TPB, gp + tid + 7 * TPB);
            cp16(s4t + tid + 7 * TPB, gt + tid + 7 * TPB);
        }
    };

    // ---- balanced contiguous chunk for this block ----
    const int b = blockIdx.x;
    const int base = NTILES / GRID;               // 21
    const int rem = NTILES % GRID;                // 112
    const int cnt = base + (b < rem ? 1 : 0);     // 21 or 22 tiles
    const int tile0 = b * base + (b < rem ? b : rem);

    float acc = 0.0f;

    // ---- prologue: 2 tiles in flight ----
    prefetch(0, tile0);
    cp_commit();
    if (cnt > 1) {
        prefetch(1, tile0 + 1);
        cp_commit();
    }

    int cur = 0;
    for (int k = 0; k < cnt; k++) {
        if (k + 1 < cnt) cp_wait1();   // tile k done; tile k+1 still in flight
        else             cp_wait0();   // last tile: it's the only group left
        __syncthreads();               // async-proxy visibility + buffer-reuse
                                       // protection for the stage we refill

        if (k + 2 < cnt) {             // keep the stream fed immediately
            int nbuf = cur + 2;
            if (nbuf >= NSTAGE) nbuf -= NSTAGE;
            prefetch(nbuf, tile0 + k + 2);
            cp_commit();
        }

        // ---- per-cell loss (thread tid owns cell tid of tile k) ----
        const float* p = sp[cur] + tid * 30;
        const float* t = st[cur] + tid * 30;

        const float coo = (t[4] > 0.0f) ? 1.0f : 0.0f;
        const float noo = 1.0f - coo;

        float d4 = p[4] - t[4];
        float d9 = p[9] - t[9];
        float loss = 0.5f * noo * (d4 * d4 + d9 * d9);

        float cls = 0.0f;
#pragma unroll
        for (int kk = 10; kk < 30; kk++) {
            float d = p[kk] - t[kk];
            cls += d * d;
        }
        loss += coo * cls;

        // degenerate IoU, matching the reference exactly:
        // inter = 1 iff (rb-lt)<0 in BOTH dims, else 0
        const float t_ltx = t[0] - 0.5f * t[2];
        const float t_lty = t[1] - 0.5f * t[3];
        const float t_rbx = t[0] + 0.5f * t[2];
        const float t_rby = t[1] + 0.5f * t[3];
        const float area2 = (t_rbx - t_ltx) * (t_rby - t_lty);

        float iou[2];
#pragma unroll
        for (int bb = 0; bb < 2; bb++) {
            const float* pb = p + bb * 5;
            float p_ltx = pb[0] - 0.5f * pb[2];
            float p_lty = pb[1] - 0.5f * pb[3];
            float p_rbx = pb[0] + 0.5f * pb[2];
            float p_rby = pb[1] + 0.5f * pb[3];
            float ltx = fmaxf(p_ltx, t_ltx);
            float lty = fmaxf(p_lty, t_lty);
            float rbx = fminf(p_rbx, t_rbx);
            float rby = fminf(p_rby, t_rby);
            float wh0 = (rbx - ltx < 0.0f) ? 1.0f : 0.0f;
            float wh1 = (rby - lty < 0.0f) ? 1.0f : 0.0f;
            float inter = wh0 * wh1;
            float area1 = (p_rbx - p_ltx) * (p_rby - p_lty);
            iou[bb] = inter / (area1 + area2 - inter);
        }
        const int idx = (iou[1] > iou[0]) ? 1 : 0;   // first index on ties
        const float* rp = p + idx * 5;
        const float* rt = t + idx * 5;

        float dc = rp[4] - rt[4];
        loss += coo * dc * dc;

        float dx = rp[0] - rt[0];
        float dy = rp[1] - rt[1];
        float wp2 = (coo > 0.0f) ? rp[2] : 1.0f;
        float wp3 = (coo > 0.0f) ? rp[3] : 1.0f;
        float wt2 = (coo > 0.0f) ? rt[2] : 1.0f;
        float wt3 = (coo > 0.0f) ? rt[3] : 1.0f;
        float dw = sqrtf(wp2) - sqrtf(wt2);
        float dh = sqrtf(wp3) - sqrtf(wt3);
        loss += 5.0f * coo * (dx * dx + dy * dy + dw * dw + dh * dh);

        acc += loss;

        cur += 1;
        if (cur == NSTAGE) cur = 0;
        // no end barrier: stage reuse is protected by the next iteration's
        // top barrier (prefetch into a stage happens only after it)
    }

    // ---- block reduction ----
#pragma unroll
    for (int o = 16; o > 0; o >>= 1)
        acc += __shfl_xor_sync(0xFFFFFFFFu, acc, o);
    if ((tid & 31) == 0)
        warpsum[tid >> 5] = acc;
    __syncthreads();

    if (tid == 0) {
        float s = warpsum[0] + warpsum[1];
        atomicAdd(&g_acc, (double)s * (1.0 / (double)N_BATCH));
        __threadfence();
        s_ticket = atomicAdd(&g_count, 1u);
    }
    __syncthreads();

    // ---- last block publishes scalar and resets state ----
    if (tid == 0 && s_ticket == GRID - 1) {
        double total = atomicAdd(&g_acc, 0.0);
        out[0] = (float)total;
        g_acc = 0.0;
        g_count = 0u;
    }
}

extern "C" void kernel_launch(void* const* d_in, const int* in_sizes, int n_in,
                              void* d_out, int out_size) {
    (void)in_sizes; (void)n_in; (void)out_size;
    const float* pred = (const float*)d_in[0];
    const float* targ = (const float*)d_in[1];
    float* out = (float*)d_out;

    yolo_loss_kernel<<<GRID, TPB>>>(pred, targ, out);
}